// round 6
// baseline (speedup 1.0000x reference)
#include <cuda_runtime.h>
#include <cstdint>

// ---------------- problem constants ----------------
#define T_TOK 2048
#define D_DIM 2048
#define N_OUT 11264
#define R_N   16
#define BD    5632

// ---------------- GEMM config ----------------
#define BM 128
#define BN 128
#define BK 32                  // K per stage (32 f32 = 128B row)
#define NST 4                  // cp.async pipeline stages
#define NSTEP (D_DIM / BK)     // 64
#define NTHREADS 512

// smem layout (byte offsets into dynamic smem)
#define OFF_LS   0             // 128 ints
#define OFF_XA   512           // 128*16 floats = 8192
#define OFF_PIPE 9216          // NST * 32768 (A 16K + B 16K per stage)
#define STAGE_BYTES 32768
#define SMEM_BYTES (OFF_PIPE + NST * STAGE_BYTES)   // 140288

__device__ float g_xa[T_TOK * 32];

// ---------------- helpers ----------------
__device__ __forceinline__ uint32_t smem_u32(const void* p) {
    uint32_t a;
    asm("{ .reg .u64 t; cvta.to.shared.u64 t, %1; cvt.u32.u64 %0, t; }" : "=r"(a) : "l"(p));
    return a;
}
#define CP_ASYNC16(dst, src) \
    asm volatile("cp.async.cg.shared.global [%0], [%1], 16;" :: "r"(dst), "l"(src) : "memory")
#define CP_COMMIT() asm volatile("cp.async.commit_group;" ::: "memory")
#define CP_WAIT2()  asm volatile("cp.async.wait_group 2;" ::: "memory")

__device__ __forceinline__ uint32_t swz(uint32_t off) { return off ^ ((off >> 3) & 0x70); }

#define LDSM_X4(r0, r1, r2, r3, addr) \
    asm volatile("ldmatrix.sync.aligned.m8n8.x4.shared.b16 {%0,%1,%2,%3}, [%4];" \
                 : "=r"(r0), "=r"(r1), "=r"(r2), "=r"(r3) : "r"(addr))

__device__ __forceinline__ uint32_t f2tf(uint32_t u) {
    uint32_t o; asm("cvt.rna.tf32.f32 %0, %1;" : "=r"(o) : "f"(__uint_as_float(u))); return o;
}
__device__ __forceinline__ void mma_tf32(float* c, const uint32_t* a, const uint32_t* b) {
    asm volatile("mma.sync.aligned.m16n8k8.row.col.f32.tf32.tf32.f32 "
        "{%0,%1,%2,%3}, {%4,%5,%6,%7}, {%8,%9}, {%0,%1,%2,%3};"
        : "+f"(c[0]), "+f"(c[1]), "+f"(c[2]), "+f"(c[3])
        : "r"(a[0]), "r"(a[1]), "r"(a[2]), "r"(a[3]), "r"(b[0]), "r"(b[1]));
}

// ---------------------------------------------------------------------------
// Kernel 1: xa[t, 0..31] = x[t,:] @ A_buffer[idx[t]]  (fp32, float4 loads)
// ---------------------------------------------------------------------------
__global__ void xa_kernel(const float* __restrict__ x,
                          const float* __restrict__ A,
                          const int* __restrict__ idx) {
    __shared__ float xs[D_DIM];
    __shared__ float red[32][36];

    const int t = blockIdx.x;
    const int l = idx[t];
    const int tid = threadIdx.x;

    const float4* xr4 = (const float4*)(x + (size_t)t * D_DIM);
#pragma unroll
    for (int i = 0; i < 2; ++i)
        ((float4*)xs)[tid + i * 256] = xr4[tid + i * 256];
    __syncthreads();

    const int rq = tid & 7;
    const int slice = tid >> 3;
    const float4* A4 = (const float4*)(A + (size_t)l * D_DIM * 32);

    float4 acc = make_float4(0.f, 0.f, 0.f, 0.f);
#pragma unroll 4
    for (int i = 0; i < 64; ++i) {
        int d = slice * 64 + i;
        float4 a = A4[(size_t)d * 8 + rq];
        float xv = xs[d];
        acc.x = fmaf(xv, a.x, acc.x);
        acc.y = fmaf(xv, a.y, acc.y);
        acc.z = fmaf(xv, a.z, acc.z);
        acc.w = fmaf(xv, a.w, acc.w);
    }
    red[slice][rq * 4 + 0] = acc.x;
    red[slice][rq * 4 + 1] = acc.y;
    red[slice][rq * 4 + 2] = acc.z;
    red[slice][rq * 4 + 3] = acc.w;
    __syncthreads();

    if (tid < 32) {
        float s = 0.f;
#pragma unroll
        for (int k = 0; k < 32; ++k) s += red[k][tid];
        g_xa[t * 32 + tid] = s;
    }
}

// ---------------------------------------------------------------------------
// Kernel 2: tf32 mma.sync GEMM, 128x128 tile, 16 warps (4x4), 32x32 warp tile
// ---------------------------------------------------------------------------
__device__ __forceinline__ void load_stage(uint32_t saA, uint32_t saB,
                                           const float* __restrict__ xg,
                                           const float* __restrict__ wg, int tid) {
#pragma unroll
    for (int i = 0; i < 2; ++i) {
        int idx = tid + i * NTHREADS;
        int row = idx >> 3, seg = idx & 7;
        CP_ASYNC16(saA + swz(row * 128 + seg * 16), xg + (size_t)row * D_DIM + seg * 4);
    }
#pragma unroll
    for (int i = 0; i < 2; ++i) {
        int idx = tid + i * NTHREADS;
        int row = idx >> 3, seg = idx & 7;
        CP_ASYNC16(saB + swz(row * 128 + seg * 16), wg + (size_t)row * D_DIM + seg * 4);
    }
}

__global__ __launch_bounds__(NTHREADS, 1)
void gemm_tc_kernel(const float* __restrict__ x,
                    const float* __restrict__ W,
                    const float* __restrict__ Bbuf,
                    const int* __restrict__ idx,
                    float* __restrict__ out) {
    extern __shared__ char sm[];
    const uint32_t sb = smem_u32(sm);

    const int tid = threadIdx.x;
    const int wid = tid >> 5, lane = tid & 31;
    const int wm = wid & 3;        // 4 warp-rows of 32
    const int wn = wid >> 2;       // 4 warp-cols of 32
    const int bm = blockIdx.y * BM;
    const int bn = blockIdx.x * BN;

    float* xa_s = (float*)(sm + OFF_XA);
    int*   ls   = (int*)(sm + OFF_LS);

    // delta metadata
    const int half = (bn >= BD) ? 1 : 0;
    for (int i = tid; i < BM * 16; i += NTHREADS) {
        int row = i >> 4, r = i & 15;
        xa_s[row * 16 + r] = g_xa[(bm + row) * 32 + half * 16 + r];
    }
    if (tid < BM) ls[tid] = idx[bm + tid];

    const float* xbase = x + (size_t)bm * D_DIM;
    const float* wbase = W + (size_t)bn * D_DIM;

    // prologue: stages 0..2
#pragma unroll
    for (int s = 0; s < NST - 1; ++s) {
        load_stage(sb + OFF_PIPE + s * STAGE_BYTES,
                   sb + OFF_PIPE + s * STAGE_BYTES + 16384,
                   xbase + s * BK, wbase + s * BK, tid);
        CP_COMMIT();
    }

    float acc[2][4][4];
#pragma unroll
    for (int mt = 0; mt < 2; ++mt)
#pragma unroll
        for (int nt = 0; nt < 4; ++nt)
#pragma unroll
            for (int j = 0; j < 4; ++j) acc[mt][nt][j] = 0.f;

    // ---- per-lane ldmatrix address components ----
    // A frag (m16 tile mt): matrix j=lane>>3: row = wm*32+mt*16+(j&1)*8+(lane&7),
    //                       col16B = (j>>1)  -> bytes kk*32 + (j>>1)*16
    // B frag (n16 pair p):  matrix j:        row = wn*32+p*16+(j>>1)*8+(lane&7),
    //                       col16B = (j&1)   -> bytes kk*32 + (j&1)*16
    const int j8 = lane >> 3, lr = lane & 7;
    uint32_t a_off[2], a_xor[2], b_off[2], b_xor[2];
    const uint32_t a_cb = (j8 >> 1) * 16;
    const uint32_t b_cb = (j8 & 1) * 16;
#pragma unroll
    for (int mt = 0; mt < 2; ++mt) {
        uint32_t row = wm * 32 + mt * 16 + (j8 & 1) * 8 + lr;
        a_off[mt] = row * 128;
        a_xor[mt] = (row & 7) << 4;
    }
#pragma unroll
    for (int p = 0; p < 2; ++p) {
        uint32_t row = wn * 32 + p * 16 + (j8 >> 1) * 8 + lr;
        b_off[p] = row * 128;
        b_xor[p] = (row & 7) << 4;
    }

    for (int s = 0; s < NSTEP; ++s) {
        CP_WAIT2();
        __syncthreads();

        if (s + NST - 1 < NSTEP) {
            int slot = (s + NST - 1) & (NST - 1);
            load_stage(sb + OFF_PIPE + slot * STAGE_BYTES,
                       sb + OFF_PIPE + slot * STAGE_BYTES + 16384,
                       xbase + (s + NST - 1) * BK, wbase + (s + NST - 1) * BK, tid);
        }
        CP_COMMIT();

        const uint32_t Asb = sb + OFF_PIPE + (s & (NST - 1)) * STAGE_BYTES;
        const uint32_t Bsb = Asb + 16384;

#pragma unroll
        for (int kk = 0; kk < 4; ++kk) {
            const uint32_t kb = kk * 32;
            uint32_t a[2][4], b[4][2];
#pragma unroll
            for (int mt = 0; mt < 2; ++mt) {
                uint32_t ad = Asb + a_off[mt] + ((kb + a_cb) ^ a_xor[mt]);
                LDSM_X4(a[mt][0], a[mt][1], a[mt][2], a[mt][3], ad);
            }
#pragma unroll
            for (int p = 0; p < 2; ++p) {
                uint32_t bd = Bsb + b_off[p] + ((kb + b_cb) ^ b_xor[p]);
                LDSM_X4(b[2 * p][0], b[2 * p][1], b[2 * p + 1][0], b[2 * p + 1][1], bd);
            }
#pragma unroll
            for (int mt = 0; mt < 2; ++mt)
#pragma unroll
                for (int q = 0; q < 4; ++q) a[mt][q] = f2tf(a[mt][q]);
#pragma unroll
            for (int nt = 0; nt < 4; ++nt) {
                b[nt][0] = f2tf(b[nt][0]);
                b[nt][1] = f2tf(b[nt][1]);
            }
#pragma unroll
            for (int mt = 0; mt < 2; ++mt)
#pragma unroll
                for (int nt = 0; nt < 4; ++nt)
                    mma_tf32(acc[mt][nt], a[mt], b[nt]);
        }
    }

    // ---- stage accumulators to smem (reuse pipeline region), padded rows ----
    __syncthreads();
    float* Cs = (float*)(sm + OFF_PIPE);
    const int mrow = lane >> 2, kcol = lane & 3;
#pragma unroll
    for (int mt = 0; mt < 2; ++mt)
#pragma unroll
        for (int nt = 0; nt < 4; ++nt) {
            int row0 = wm * 32 + mt * 16 + mrow;
            int col  = wn * 32 + nt * 8 + kcol * 2;
            *(float2*)&Cs[row0 * 132 + col]       = make_float2(acc[mt][nt][0], acc[mt][nt][1]);
            *(float2*)&Cs[(row0 + 8) * 132 + col] = make_float2(acc[mt][nt][2], acc[mt][nt][3]);
        }
    __syncthreads();

    // ---- epilogue: thread -> (row = tid>>2, 32-col quarter), fused LoRA delta
    {
        const int row = tid >> 2;
        const int ch  = (tid & 3) * 32;
        const int l   = ls[row];

        float v[32];
#pragma unroll
        for (int j = 0; j < 8; ++j) {
            float4 t4 = *(const float4*)&Cs[row * 132 + ch + 4 * j];
            v[4 * j] = t4.x; v[4 * j + 1] = t4.y; v[4 * j + 2] = t4.z; v[4 * j + 3] = t4.w;
        }
        const float* xav = &xa_s[row * 16];
        const float* Bp = Bbuf + (size_t)l * 16 * N_OUT + bn + ch;
#pragma unroll
        for (int r = 0; r < R_N; ++r) {
            float xv = xav[r];
            const float4* B4 = (const float4*)(Bp + (size_t)r * N_OUT);
#pragma unroll
            for (int j = 0; j < 8; ++j) {
                float4 bb = B4[j];
                v[4 * j + 0] = fmaf(xv, bb.x, v[4 * j + 0]);
                v[4 * j + 1] = fmaf(xv, bb.y, v[4 * j + 1]);
                v[4 * j + 2] = fmaf(xv, bb.z, v[4 * j + 2]);
                v[4 * j + 3] = fmaf(xv, bb.w, v[4 * j + 3]);
            }
        }
        float* op = out + (size_t)(bm + row) * N_OUT + bn + ch;
#pragma unroll
        for (int j = 0; j < 8; ++j)
            ((float4*)op)[j] = make_float4(v[4 * j], v[4 * j + 1], v[4 * j + 2], v[4 * j + 3]);
    }
}

// ---------------------------------------------------------------------------
extern "C" void kernel_launch(void* const* d_in, const int* in_sizes, int n_in,
                              void* d_out, int out_size) {
    const float* x    = (const float*)d_in[0];
    const float* W    = (const float*)d_in[1];
    const float* Abuf = (const float*)d_in[2];
    const float* Bbuf = (const float*)d_in[3];
    const int*   idx  = (const int*)d_in[4];
    float*       out  = (float*)d_out;

    cudaFuncSetAttribute(gemm_tc_kernel,
                         cudaFuncAttributeMaxDynamicSharedMemorySize, SMEM_BYTES);

    xa_kernel<<<T_TOK, 256>>>(x, Abuf, idx);

    dim3 grid(N_OUT / BN, T_TOK / BM);   // 88 x 16
    gemm_tc_kernel<<<grid, NTHREADS, SMEM_BYTES>>>(x, W, Bbuf, idx, out);
}

// round 7
// speedup vs baseline: 1.0386x; 1.0386x over previous
#include <cuda_runtime.h>
#include <cstdint>

// ---------------- problem constants ----------------
#define T_TOK 2048
#define D_DIM 2048
#define N_OUT 11264
#define R_N   16
#define BD    5632

// ---------------- GEMM config ----------------
#define BM 128
#define BN 128
#define BK 32                  // K per stage (32 f32 = 128B row)
#define NST 4                  // cp.async pipeline stages
#define NSTEP (D_DIM / BK)     // 64
#define NTHREADS 512

// smem layout (byte offsets into dynamic smem)
#define OFF_LS   0             // 128 ints
#define OFF_XA   512           // 128*16 floats = 8192
#define OFF_PIPE 9216          // NST * 32768 (A 16K + B 16K per stage)
#define STAGE_BYTES 32768
#define SMEM_BYTES (OFF_PIPE + NST * STAGE_BYTES)   // 140288

__device__ float g_xa[T_TOK * 32];
__device__ float g_x32[(size_t)T_TOK * D_DIM];   // x pre-rounded to tf32
__device__ float g_w32[(size_t)N_OUT * D_DIM];   // W pre-rounded to tf32

// ---------------- helpers ----------------
__device__ __forceinline__ uint32_t smem_u32(const void* p) {
    uint32_t a;
    asm("{ .reg .u64 t; cvta.to.shared.u64 t, %1; cvt.u32.u64 %0, t; }" : "=r"(a) : "l"(p));
    return a;
}
#define CP_ASYNC16(dst, src) \
    asm volatile("cp.async.cg.shared.global [%0], [%1], 16;" :: "r"(dst), "l"(src) : "memory")
#define CP_COMMIT() asm volatile("cp.async.commit_group;" ::: "memory")
#define CP_WAIT2()  asm volatile("cp.async.wait_group 2;" ::: "memory")

__device__ __forceinline__ uint32_t swz(uint32_t off) { return off ^ ((off >> 3) & 0x70); }

#define LDSM_X4(r0, r1, r2, r3, addr) \
    asm volatile("ldmatrix.sync.aligned.m8n8.x4.shared.b16 {%0,%1,%2,%3}, [%4];" \
                 : "=r"(r0), "=r"(r1), "=r"(r2), "=r"(r3) : "r"(addr))

__device__ __forceinline__ void mma_tf32(float* c, const uint32_t* a, const uint32_t* b) {
    asm volatile("mma.sync.aligned.m16n8k8.row.col.f32.tf32.tf32.f32 "
        "{%0,%1,%2,%3}, {%4,%5,%6,%7}, {%8,%9}, {%0,%1,%2,%3};"
        : "+f"(c[0]), "+f"(c[1]), "+f"(c[2]), "+f"(c[3])
        : "r"(a[0]), "r"(a[1]), "r"(a[2]), "r"(a[3]), "r"(b[0]), "r"(b[1]));
}

// ---------------------------------------------------------------------------
// Kernel 0: round x and W to tf32 (RN) once; mainloop HW truncation is then
// the identity, so no per-fragment cvt is needed.
// ---------------------------------------------------------------------------
__global__ void cvt_kernel(const float* __restrict__ x, const float* __restrict__ W) {
    const size_t NX4 = (size_t)T_TOK * D_DIM / 4;
    const size_t NW4 = (size_t)N_OUT * D_DIM / 4;
    const size_t stride = (size_t)gridDim.x * blockDim.x;
    for (size_t p = (size_t)blockIdx.x * blockDim.x + threadIdx.x; p < NX4 + NW4; p += stride) {
        float4 v = (p < NX4) ? ((const float4*)x)[p] : ((const float4*)W)[p - NX4];
        uint32_t r0, r1, r2, r3;
        asm("cvt.rna.tf32.f32 %0, %1;" : "=r"(r0) : "f"(v.x));
        asm("cvt.rna.tf32.f32 %0, %1;" : "=r"(r1) : "f"(v.y));
        asm("cvt.rna.tf32.f32 %0, %1;" : "=r"(r2) : "f"(v.z));
        asm("cvt.rna.tf32.f32 %0, %1;" : "=r"(r3) : "f"(v.w));
        float4 o = make_float4(__uint_as_float(r0), __uint_as_float(r1),
                               __uint_as_float(r2), __uint_as_float(r3));
        float4* dst = (p < NX4) ? ((float4*)g_x32) + p : ((float4*)g_w32) + (p - NX4);
        *dst = o;
    }
}

// ---------------------------------------------------------------------------
// Kernel 1: xa[t, 0..31] = x[t,:] @ A_buffer[idx[t]]  (fp32, float4 loads)
// ---------------------------------------------------------------------------
__global__ void xa_kernel(const float* __restrict__ x,
                          const float* __restrict__ A,
                          const int* __restrict__ idx) {
    __shared__ float xs[D_DIM];
    __shared__ float red[32][36];

    const int t = blockIdx.x;
    const int l = idx[t];
    const int tid = threadIdx.x;

    const float4* xr4 = (const float4*)(x + (size_t)t * D_DIM);
#pragma unroll
    for (int i = 0; i < 2; ++i)
        ((float4*)xs)[tid + i * 256] = xr4[tid + i * 256];
    __syncthreads();

    const int rq = tid & 7;
    const int slice = tid >> 3;
    const float4* A4 = (const float4*)(A + (size_t)l * D_DIM * 32);

    float4 acc = make_float4(0.f, 0.f, 0.f, 0.f);
#pragma unroll 4
    for (int i = 0; i < 64; ++i) {
        int d = slice * 64 + i;
        float4 a = A4[(size_t)d * 8 + rq];
        float xv = xs[d];
        acc.x = fmaf(xv, a.x, acc.x);
        acc.y = fmaf(xv, a.y, acc.y);
        acc.z = fmaf(xv, a.z, acc.z);
        acc.w = fmaf(xv, a.w, acc.w);
    }
    red[slice][rq * 4 + 0] = acc.x;
    red[slice][rq * 4 + 1] = acc.y;
    red[slice][rq * 4 + 2] = acc.z;
    red[slice][rq * 4 + 3] = acc.w;
    __syncthreads();

    if (tid < 32) {
        float s = 0.f;
#pragma unroll
        for (int k = 0; k < 32; ++k) s += red[k][tid];
        g_xa[t * 32 + tid] = s;
    }
}

// ---------------------------------------------------------------------------
// Kernel 2: tf32 mma.sync GEMM, 128x128 tile, 16 warps (4x4), 32x32 warp tile
// ---------------------------------------------------------------------------
__device__ __forceinline__ void load_stage(uint32_t saA, uint32_t saB,
                                           const float* __restrict__ xg,
                                           const float* __restrict__ wg, int tid) {
#pragma unroll
    for (int i = 0; i < 2; ++i) {
        int idx = tid + i * NTHREADS;
        int row = idx >> 3, seg = idx & 7;
        CP_ASYNC16(saA + swz(row * 128 + seg * 16), xg + (size_t)row * D_DIM + seg * 4);
    }
#pragma unroll
    for (int i = 0; i < 2; ++i) {
        int idx = tid + i * NTHREADS;
        int row = idx >> 3, seg = idx & 7;
        CP_ASYNC16(saB + swz(row * 128 + seg * 16), wg + (size_t)row * D_DIM + seg * 4);
    }
}

__global__ __launch_bounds__(NTHREADS, 1)
void gemm_tc_kernel(const float* __restrict__ Bbuf,
                    const int* __restrict__ idx,
                    float* __restrict__ out) {
    extern __shared__ char sm[];
    const uint32_t sb = smem_u32(sm);

    const int tid = threadIdx.x;
    const int wid = tid >> 5, lane = tid & 31;
    const int wm = wid & 3;        // 4 warp-rows of 32
    const int wn = wid >> 2;       // 4 warp-cols of 32
    const int bm = blockIdx.y * BM;
    const int bn = blockIdx.x * BN;

    float* xa_s = (float*)(sm + OFF_XA);
    int*   ls   = (int*)(sm + OFF_LS);

    // delta metadata
    const int half = (bn >= BD) ? 1 : 0;
    for (int i = tid; i < BM * 16; i += NTHREADS) {
        int row = i >> 4, r = i & 15;
        xa_s[row * 16 + r] = g_xa[(bm + row) * 32 + half * 16 + r];
    }
    if (tid < BM) ls[tid] = idx[bm + tid];

    const float* xbase = g_x32 + (size_t)bm * D_DIM;
    const float* wbase = g_w32 + (size_t)bn * D_DIM;

    // prologue: stages 0..2
#pragma unroll
    for (int s = 0; s < NST - 1; ++s) {
        load_stage(sb + OFF_PIPE + s * STAGE_BYTES,
                   sb + OFF_PIPE + s * STAGE_BYTES + 16384,
                   xbase + s * BK, wbase + s * BK, tid);
        CP_COMMIT();
    }

    float acc[2][4][4];
#pragma unroll
    for (int mt = 0; mt < 2; ++mt)
#pragma unroll
        for (int nt = 0; nt < 4; ++nt)
#pragma unroll
            for (int j = 0; j < 4; ++j) acc[mt][nt][j] = 0.f;

    // ---- per-lane ldmatrix address components (layouts validated R4/R5) ----
    const int j8 = lane >> 3, lr = lane & 7;
    uint32_t a_off[2], a_xor[2], b_off[2], b_xor[2];
    const uint32_t a_cb = (j8 >> 1) * 16;
    const uint32_t b_cb = (j8 & 1) * 16;
#pragma unroll
    for (int mt = 0; mt < 2; ++mt) {
        uint32_t row = wm * 32 + mt * 16 + (j8 & 1) * 8 + lr;
        a_off[mt] = row * 128;
        a_xor[mt] = (row & 7) << 4;
    }
#pragma unroll
    for (int p = 0; p < 2; ++p) {
        uint32_t row = wn * 32 + p * 16 + (j8 >> 1) * 8 + lr;
        b_off[p] = row * 128;
        b_xor[p] = (row & 7) << 4;
    }

    for (int s = 0; s < NSTEP; ++s) {
        CP_WAIT2();
        __syncthreads();

        if (s + NST - 1 < NSTEP) {
            int slot = (s + NST - 1) & (NST - 1);
            load_stage(sb + OFF_PIPE + slot * STAGE_BYTES,
                       sb + OFF_PIPE + slot * STAGE_BYTES + 16384,
                       xbase + (s + NST - 1) * BK, wbase + (s + NST - 1) * BK, tid);
        }
        CP_COMMIT();

        const uint32_t Asb = sb + OFF_PIPE + (s & (NST - 1)) * STAGE_BYTES;
        const uint32_t Bsb = Asb + 16384;

#pragma unroll
        for (int kk = 0; kk < 4; ++kk) {
            const uint32_t kb = kk * 32;
            uint32_t a[2][4], b[4][2];
#pragma unroll
            for (int mt = 0; mt < 2; ++mt) {
                uint32_t ad = Asb + a_off[mt] + ((kb + a_cb) ^ a_xor[mt]);
                LDSM_X4(a[mt][0], a[mt][1], a[mt][2], a[mt][3], ad);
            }
#pragma unroll
            for (int p = 0; p < 2; ++p) {
                uint32_t bd = Bsb + b_off[p] + ((kb + b_cb) ^ b_xor[p]);
                LDSM_X4(b[2 * p][0], b[2 * p][1], b[2 * p + 1][0], b[2 * p + 1][1], bd);
            }
            // inputs already tf32-rounded -> HW truncation is identity, no cvt
#pragma unroll
            for (int mt = 0; mt < 2; ++mt)
#pragma unroll
                for (int nt = 0; nt < 4; ++nt)
                    mma_tf32(acc[mt][nt], a[mt], b[nt]);
        }
    }

    // ---- stage accumulators to smem (reuse pipeline region), padded rows ----
    __syncthreads();
    float* Cs = (float*)(sm + OFF_PIPE);
    const int mrow = lane >> 2, kcol = lane & 3;
#pragma unroll
    for (int mt = 0; mt < 2; ++mt)
#pragma unroll
        for (int nt = 0; nt < 4; ++nt) {
            int row0 = wm * 32 + mt * 16 + mrow;
            int col  = wn * 32 + nt * 8 + kcol * 2;
            *(float2*)&Cs[row0 * 132 + col]       = make_float2(acc[mt][nt][0], acc[mt][nt][1]);
            *(float2*)&Cs[(row0 + 8) * 132 + col] = make_float2(acc[mt][nt][2], acc[mt][nt][3]);
        }
    __syncthreads();

    // ---- epilogue: thread -> (row = tid>>2, 32-col quarter), fused LoRA delta
    {
        const int row = tid >> 2;
        const int ch  = (tid & 3) * 32;
        const int l   = ls[row];

        float v[32];
#pragma unroll
        for (int j = 0; j < 8; ++j) {
            float4 t4 = *(const float4*)&Cs[row * 132 + ch + 4 * j];
            v[4 * j] = t4.x; v[4 * j + 1] = t4.y; v[4 * j + 2] = t4.z; v[4 * j + 3] = t4.w;
        }
        const float* xav = &xa_s[row * 16];
        const float* Bp = Bbuf + (size_t)l * 16 * N_OUT + bn + ch;
#pragma unroll
        for (int r = 0; r < R_N; ++r) {
            float xv = xav[r];
            const float4* B4 = (const float4*)(Bp + (size_t)r * N_OUT);
#pragma unroll
            for (int j = 0; j < 8; ++j) {
                float4 bb = B4[j];
                v[4 * j + 0] = fmaf(xv, bb.x, v[4 * j + 0]);
                v[4 * j + 1] = fmaf(xv, bb.y, v[4 * j + 1]);
                v[4 * j + 2] = fmaf(xv, bb.z, v[4 * j + 2]);
                v[4 * j + 3] = fmaf(xv, bb.w, v[4 * j + 3]);
            }
        }
        float* op = out + (size_t)(bm + row) * N_OUT + bn + ch;
#pragma unroll
        for (int j = 0; j < 8; ++j)
            ((float4*)op)[j] = make_float4(v[4 * j], v[4 * j + 1], v[4 * j + 2], v[4 * j + 3]);
    }
}

// ---------------------------------------------------------------------------
extern "C" void kernel_launch(void* const* d_in, const int* in_sizes, int n_in,
                              void* d_out, int out_size) {
    const float* x    = (const float*)d_in[0];
    const float* W    = (const float*)d_in[1];
    const float* Abuf = (const float*)d_in[2];
    const float* Bbuf = (const float*)d_in[3];
    const int*   idx  = (const int*)d_in[4];
    float*       out  = (float*)d_out;

    cudaFuncSetAttribute(gemm_tc_kernel,
                         cudaFuncAttributeMaxDynamicSharedMemorySize, SMEM_BYTES);

    cvt_kernel<<<1024, 256>>>(x, W);
    xa_kernel<<<T_TOK, 256>>>(x, Abuf, idx);

    dim3 grid(N_OUT / BN, T_TOK / BM);   // 88 x 16
    gemm_tc_kernel<<<grid, NTHREADS, SMEM_BYTES>>>(Bbuf, idx, out);
}

// round 9
// speedup vs baseline: 1.2466x; 1.2002x over previous
#include <cuda_runtime.h>
#include <cstdint>

// ---------------- problem constants ----------------
#define T_TOK 2048
#define D_DIM 2048
#define N_OUT 11264
#define R_N   16
#define BD    5632

// ---------------- GEMM config ----------------
#define BM 128
#define BN 128
#define BK 32                  // K per stage (32 f32 = 128B row)
#define NST 3                  // cp.async pipeline stages
#define NSTEP (D_DIM / BK)     // 64
#define NTHREADS 256

// smem layout (byte offsets into dynamic smem)
#define OFF_LS   0             // 128 ints
#define OFF_XA   512           // 128*16 floats = 8192
#define OFF_PIPE 9216          // NST * 32768 (A 16K + B 16K per stage)
#define STAGE_BYTES 32768
#define SMEM_BYTES (OFF_PIPE + NST * STAGE_BYTES)   // 107520 -> 2 CTAs/SM

__device__ float g_xa[T_TOK * 32];
__device__ float g_x32[(size_t)T_TOK * D_DIM];   // x pre-rounded to tf32
__device__ float g_w32[(size_t)N_OUT * D_DIM];   // W pre-rounded to tf32

// ---------------- helpers ----------------
__device__ __forceinline__ uint32_t smem_u32(const void* p) {
    uint32_t a;
    asm("{ .reg .u64 t; cvta.to.shared.u64 t, %1; cvt.u32.u64 %0, t; }" : "=r"(a) : "l"(p));
    return a;
}
#define CP_ASYNC16(dst, src) \
    asm volatile("cp.async.cg.shared.global [%0], [%1], 16;" :: "r"(dst), "l"(src) : "memory")
#define CP_COMMIT() asm volatile("cp.async.commit_group;" ::: "memory")
#define CP_WAIT1()  asm volatile("cp.async.wait_group 1;" ::: "memory")

__device__ __forceinline__ uint32_t swz(uint32_t off) { return off ^ ((off >> 3) & 0x70); }

#define LDSM_X4(r0, r1, r2, r3, addr) \
    asm volatile("ldmatrix.sync.aligned.m8n8.x4.shared.b16 {%0,%1,%2,%3}, [%4];" \
                 : "=r"(r0), "=r"(r1), "=r"(r2), "=r"(r3) : "r"(addr))

__device__ __forceinline__ void mma_tf32(float* c, const uint32_t* a, const uint32_t* b) {
    asm volatile("mma.sync.aligned.m16n8k8.row.col.f32.tf32.tf32.f32 "
        "{%0,%1,%2,%3}, {%4,%5,%6,%7}, {%8,%9}, {%0,%1,%2,%3};"
        : "+f"(c[0]), "+f"(c[1]), "+f"(c[2]), "+f"(c[3])
        : "r"(a[0]), "r"(a[1]), "r"(a[2]), "r"(a[3]), "r"(b[0]), "r"(b[1]));
}

// ---------------------------------------------------------------------------
// Kernel 0: round x and W to tf32 (RN) once; mainloop HW truncation is then
// the identity, so no per-fragment cvt is needed.
// ---------------------------------------------------------------------------
__global__ void cvt_kernel(const float* __restrict__ x, const float* __restrict__ W) {
    const size_t NX4 = (size_t)T_TOK * D_DIM / 4;
    const size_t NW4 = (size_t)N_OUT * D_DIM / 4;
    const size_t stride = (size_t)gridDim.x * blockDim.x;
    for (size_t p = (size_t)blockIdx.x * blockDim.x + threadIdx.x; p < NX4 + NW4; p += stride) {
        float4 v = (p < NX4) ? ((const float4*)x)[p] : ((const float4*)W)[p - NX4];
        uint32_t r0, r1, r2, r3;
        asm("cvt.rna.tf32.f32 %0, %1;" : "=r"(r0) : "f"(v.x));
        asm("cvt.rna.tf32.f32 %0, %1;" : "=r"(r1) : "f"(v.y));
        asm("cvt.rna.tf32.f32 %0, %1;" : "=r"(r2) : "f"(v.z));
        asm("cvt.rna.tf32.f32 %0, %1;" : "=r"(r3) : "f"(v.w));
        float4 o = make_float4(__uint_as_float(r0), __uint_as_float(r1),
                               __uint_as_float(r2), __uint_as_float(r3));
        float4* dst = (p < NX4) ? ((float4*)g_x32) + p : ((float4*)g_w32) + (p - NX4);
        *dst = o;
    }
}

// ---------------------------------------------------------------------------
// Kernel 1: xa[t, 0..31] = x[t,:] @ A_buffer[idx[t]]  (fp32, float4 loads)
// ---------------------------------------------------------------------------
__global__ void xa_kernel(const float* __restrict__ x,
                          const float* __restrict__ A,
                          const int* __restrict__ idx) {
    __shared__ float xs[D_DIM];
    __shared__ float red[32][36];

    const int t = blockIdx.x;
    const int l = idx[t];
    const int tid = threadIdx.x;

    const float4* xr4 = (const float4*)(x + (size_t)t * D_DIM);
#pragma unroll
    for (int i = 0; i < 2; ++i)
        ((float4*)xs)[tid + i * 256] = xr4[tid + i * 256];
    __syncthreads();

    const int rq = tid & 7;
    const int slice = tid >> 3;
    const float4* A4 = (const float4*)(A + (size_t)l * D_DIM * 32);

    float4 acc = make_float4(0.f, 0.f, 0.f, 0.f);
#pragma unroll 4
    for (int i = 0; i < 64; ++i) {
        int d = slice * 64 + i;
        float4 a = A4[(size_t)d * 8 + rq];
        float xv = xs[d];
        acc.x = fmaf(xv, a.x, acc.x);
        acc.y = fmaf(xv, a.y, acc.y);
        acc.z = fmaf(xv, a.z, acc.z);
        acc.w = fmaf(xv, a.w, acc.w);
    }
    red[slice][rq * 4 + 0] = acc.x;
    red[slice][rq * 4 + 1] = acc.y;
    red[slice][rq * 4 + 2] = acc.z;
    red[slice][rq * 4 + 3] = acc.w;
    __syncthreads();

    if (tid < 32) {
        float s = 0.f;
#pragma unroll
        for (int k = 0; k < 32; ++k) s += red[k][tid];
        g_xa[t * 32 + tid] = s;
    }
}

// ---------------------------------------------------------------------------
// Kernel 2: tf32 mma.sync GEMM, 128x128 tile, 8 warps (2x4), 64x32 warp tile,
// 256 threads, 2 CTAs/SM (two independent barrier domains per SM).
// ---------------------------------------------------------------------------
__device__ __forceinline__ void load_stage(uint32_t saA, uint32_t saB,
                                           const float* __restrict__ xg,
                                           const float* __restrict__ wg, int tid) {
#pragma unroll
    for (int i = 0; i < 4; ++i) {
        int idx = tid + i * NTHREADS;
        int row = idx >> 3, seg = idx & 7;
        CP_ASYNC16(saA + swz(row * 128 + seg * 16), xg + (size_t)row * D_DIM + seg * 4);
    }
#pragma unroll
    for (int i = 0; i < 4; ++i) {
        int idx = tid + i * NTHREADS;
        int row = idx >> 3, seg = idx & 7;
        CP_ASYNC16(saB + swz(row * 128 + seg * 16), wg + (size_t)row * D_DIM + seg * 4);
    }
}

__global__ __launch_bounds__(NTHREADS, 2)
void gemm_tc_kernel(const float* __restrict__ Bbuf,
                    const int* __restrict__ idx,
                    float* __restrict__ out) {
    extern __shared__ char sm[];
    const uint32_t sb = smem_u32(sm);

    const int tid = threadIdx.x;
    const int wid = tid >> 5, lane = tid & 31;
    const int wm = wid & 1;        // 2 warp-rows of 64
    const int wn = wid >> 1;       // 4 warp-cols of 32
    const int bm = blockIdx.y * BM;
    const int bn = blockIdx.x * BN;

    float* xa_s = (float*)(sm + OFF_XA);
    int*   ls   = (int*)(sm + OFF_LS);

    // delta metadata
    const int half = (bn >= BD) ? 1 : 0;
    for (int i = tid; i < BM * 16; i += NTHREADS) {
        int row = i >> 4, r = i & 15;
        xa_s[row * 16 + r] = g_xa[(bm + row) * 32 + half * 16 + r];
    }
    if (tid < BM) ls[tid] = idx[bm + tid];

    const float* xbase = g_x32 + (size_t)bm * D_DIM;
    const float* wbase = g_w32 + (size_t)bn * D_DIM;

    // prologue: stages 0..1
#pragma unroll
    for (int s = 0; s < NST - 1; ++s) {
        load_stage(sb + OFF_PIPE + s * STAGE_BYTES,
                   sb + OFF_PIPE + s * STAGE_BYTES + 16384,
                   xbase + s * BK, wbase + s * BK, tid);
        CP_COMMIT();
    }

    float acc[4][4][4];
#pragma unroll
    for (int mt = 0; mt < 4; ++mt)
#pragma unroll
        for (int nt = 0; nt < 4; ++nt)
#pragma unroll
            for (int j = 0; j < 4; ++j) acc[mt][nt][j] = 0.f;

    // ---- per-lane ldmatrix address components (layouts validated R4..R6) ----
    const int j8 = lane >> 3, lr = lane & 7;
    uint32_t a_off[4], a_xor[4], b_off[2], b_xor[2];
    const uint32_t a_cb = (j8 >> 1) * 16;
    const uint32_t b_cb = (j8 & 1) * 16;
#pragma unroll
    for (int mt = 0; mt < 4; ++mt) {
        uint32_t row = wm * 64 + mt * 16 + (j8 & 1) * 8 + lr;
        a_off[mt] = row * 128;
        a_xor[mt] = (row & 7) << 4;
    }
#pragma unroll
    for (int p = 0; p < 2; ++p) {
        uint32_t row = wn * 32 + p * 16 + (j8 >> 1) * 8 + lr;
        b_off[p] = row * 128;
        b_xor[p] = (row & 7) << 4;
    }

    int slot = 0;                        // stage slot of iteration s
    for (int s = 0; s < NSTEP; ++s) {
        CP_WAIT1();
        __syncthreads();

        if (s + NST - 1 < NSTEP) {
            int ld = slot + (NST - 1); if (ld >= NST) ld -= NST;
            load_stage(sb + OFF_PIPE + ld * STAGE_BYTES,
                       sb + OFF_PIPE + ld * STAGE_BYTES + 16384,
                       xbase + (s + NST - 1) * BK, wbase + (s + NST - 1) * BK, tid);
        }
        CP_COMMIT();

        const uint32_t Asb = sb + OFF_PIPE + slot * STAGE_BYTES;
        const uint32_t Bsb = Asb + 16384;

#pragma unroll
        for (int kk = 0; kk < 4; ++kk) {
            const uint32_t kb = kk * 32;
            uint32_t a[4][4], b[4][2];
#pragma unroll
            for (int mt = 0; mt < 4; ++mt) {
                uint32_t ad = Asb + a_off[mt] + ((kb + a_cb) ^ a_xor[mt]);
                LDSM_X4(a[mt][0], a[mt][1], a[mt][2], a[mt][3], ad);
            }
#pragma unroll
            for (int p = 0; p < 2; ++p) {
                uint32_t bd = Bsb + b_off[p] + ((kb + b_cb) ^ b_xor[p]);
                LDSM_X4(b[2 * p][0], b[2 * p][1], b[2 * p + 1][0], b[2 * p + 1][1], bd);
            }
#pragma unroll
            for (int mt = 0; mt < 4; ++mt)
#pragma unroll
                for (int nt = 0; nt < 4; ++nt)
                    mma_tf32(acc[mt][nt], a[mt], b[nt]);
        }
        if (++slot == NST) slot = 0;
        __syncthreads();   // compute done before next iteration's loads overwrite
    }

    // ---- stage accumulators to smem (reuse pipeline region), padded rows ----
    float* Cs = (float*)(sm + OFF_PIPE);
    const int mrow = lane >> 2, kcol = lane & 3;
#pragma unroll
    for (int mt = 0; mt < 4; ++mt)
#pragma unroll
        for (int nt = 0; nt < 4; ++nt) {
            int row0 = wm * 64 + mt * 16 + mrow;
            int col  = wn * 32 + nt * 8 + kcol * 2;
            *(float2*)&Cs[row0 * 132 + col]       = make_float2(acc[mt][nt][0], acc[mt][nt][1]);
            *(float2*)&Cs[(row0 + 8) * 132 + col] = make_float2(acc[mt][nt][2], acc[mt][nt][3]);
        }
    __syncthreads();

    // ---- epilogue: row = tid>>1; two 32-col passes (v[32] keeps regs <=128)
    {
        const int row = tid >> 1;
        const int l   = ls[row];
        const float* xav = &xa_s[row * 16];

#pragma unroll
        for (int pass = 0; pass < 2; ++pass) {
            const int ch = (tid & 1) * 64 + pass * 32;
            float v[32];
#pragma unroll
            for (int j = 0; j < 8; ++j) {
                float4 t4 = *(const float4*)&Cs[row * 132 + ch + 4 * j];
                v[4 * j] = t4.x; v[4 * j + 1] = t4.y; v[4 * j + 2] = t4.z; v[4 * j + 3] = t4.w;
            }
            const float* Bp = Bbuf + (size_t)l * 16 * N_OUT + bn + ch;
#pragma unroll
            for (int r = 0; r < R_N; ++r) {
                float xv = xav[r];
                const float4* B4 = (const float4*)(Bp + (size_t)r * N_OUT);
#pragma unroll
                for (int j = 0; j < 8; ++j) {
                    float4 bb = B4[j];
                    v[4 * j + 0] = fmaf(xv, bb.x, v[4 * j + 0]);
                    v[4 * j + 1] = fmaf(xv, bb.y, v[4 * j + 1]);
                    v[4 * j + 2] = fmaf(xv, bb.z, v[4 * j + 2]);
                    v[4 * j + 3] = fmaf(xv, bb.w, v[4 * j + 3]);
                }
            }
            float* op = out + (size_t)(bm + row) * N_OUT + bn + ch;
#pragma unroll
            for (int j = 0; j < 8; ++j)
                ((float4*)op)[j] = make_float4(v[4 * j], v[4 * j + 1],
                                               v[4 * j + 2], v[4 * j + 3]);
        }
    }
}

// ---------------------------------------------------------------------------
extern "C" void kernel_launch(void* const* d_in, const int* in_sizes, int n_in,
                              void* d_out, int out_size) {
    const float* x    = (const float*)d_in[0];
    const float* W    = (const float*)d_in[1];
    const float* Abuf = (const float*)d_in[2];
    const float* Bbuf = (const float*)d_in[3];
    const int*   idx  = (const int*)d_in[4];
    float*       out  = (float*)d_out;

    cudaFuncSetAttribute(gemm_tc_kernel,
                         cudaFuncAttributeMaxDynamicSharedMemorySize, SMEM_BYTES);

    cvt_kernel<<<1024, 256>>>(x, W);
    xa_kernel<<<T_TOK, 256>>>(x, Abuf, idx);

    dim3 grid(N_OUT / BN, T_TOK / BM);   // 88 x 16
    gemm_tc_kernel<<<grid, NTHREADS, SMEM_BYTES>>>(Bbuf, idx, out);
}

// round 10
// speedup vs baseline: 1.2930x; 1.0373x over previous
#include <cuda_runtime.h>
#include <cstdint>

// ---------------- problem constants ----------------
#define T_TOK 2048
#define D_DIM 2048
#define N_OUT 11264
#define R_N   16
#define BD    5632

// ---------------- GEMM config ----------------
#define BM 128
#define BN 128
#define BK 32                  // K per stage (32 f32 = 128B row)
#define NST 3                  // cp.async pipeline stages
#define NSTEP (D_DIM / BK)     // 64
#define NTHREADS 128           // 4 warps, 64x64 warp tiles (2x2)

// smem layout (byte offsets into dynamic smem)
#define OFF_LS   0             // 128 ints
#define OFF_XA   512           // 128*16 floats = 8192
#define OFF_PIPE 9216          // NST * 32768 (A 16K + B 16K per stage)
#define STAGE_BYTES 32768
#define SMEM_BYTES (OFF_PIPE + NST * STAGE_BYTES)   // 107520 -> 2 CTAs/SM

__device__ float g_xa[T_TOK * 32];
__device__ float g_x32[(size_t)T_TOK * D_DIM];   // x pre-rounded to tf32
__device__ float g_w32[(size_t)N_OUT * D_DIM];   // W pre-rounded to tf32

// ---------------- helpers ----------------
__device__ __forceinline__ uint32_t smem_u32(const void* p) {
    uint32_t a;
    asm("{ .reg .u64 t; cvta.to.shared.u64 t, %1; cvt.u32.u64 %0, t; }" : "=r"(a) : "l"(p));
    return a;
}
#define CP_ASYNC16(dst, src) \
    asm volatile("cp.async.cg.shared.global [%0], [%1], 16;" :: "r"(dst), "l"(src) : "memory")
#define CP_COMMIT() asm volatile("cp.async.commit_group;" ::: "memory")
#define CP_WAIT1()  asm volatile("cp.async.wait_group 1;" ::: "memory")

__device__ __forceinline__ uint32_t swz(uint32_t off) { return off ^ ((off >> 3) & 0x70); }

#define LDSM_X4(r0, r1, r2, r3, addr) \
    asm volatile("ldmatrix.sync.aligned.m8n8.x4.shared.b16 {%0,%1,%2,%3}, [%4];" \
                 : "=r"(r0), "=r"(r1), "=r"(r2), "=r"(r3) : "r"(addr))

__device__ __forceinline__ void mma_tf32(float* c, const uint32_t* a, const uint32_t* b) {
    asm volatile("mma.sync.aligned.m16n8k8.row.col.f32.tf32.tf32.f32 "
        "{%0,%1,%2,%3}, {%4,%5,%6,%7}, {%8,%9}, {%0,%1,%2,%3};"
        : "+f"(c[0]), "+f"(c[1]), "+f"(c[2]), "+f"(c[3])
        : "r"(a[0]), "r"(a[1]), "r"(a[2]), "r"(a[3]), "r"(b[0]), "r"(b[1]));
}

// ---------------------------------------------------------------------------
// Kernel 0: round x and W to tf32 (RN) once; mainloop HW truncation is then
// the identity, so no per-fragment cvt is needed.
// ---------------------------------------------------------------------------
__global__ void cvt_kernel(const float* __restrict__ x, const float* __restrict__ W) {
    const size_t NX4 = (size_t)T_TOK * D_DIM / 4;
    const size_t NW4 = (size_t)N_OUT * D_DIM / 4;
    const size_t stride = (size_t)gridDim.x * blockDim.x;
    for (size_t p = (size_t)blockIdx.x * blockDim.x + threadIdx.x; p < NX4 + NW4; p += stride) {
        float4 v = (p < NX4) ? ((const float4*)x)[p] : ((const float4*)W)[p - NX4];
        uint32_t r0, r1, r2, r3;
        asm("cvt.rna.tf32.f32 %0, %1;" : "=r"(r0) : "f"(v.x));
        asm("cvt.rna.tf32.f32 %0, %1;" : "=r"(r1) : "f"(v.y));
        asm("cvt.rna.tf32.f32 %0, %1;" : "=r"(r2) : "f"(v.z));
        asm("cvt.rna.tf32.f32 %0, %1;" : "=r"(r3) : "f"(v.w));
        float4 o = make_float4(__uint_as_float(r0), __uint_as_float(r1),
                               __uint_as_float(r2), __uint_as_float(r3));
        float4* dst = (p < NX4) ? ((float4*)g_x32) + p : ((float4*)g_w32) + (p - NX4);
        *dst = o;
    }
}

// ---------------------------------------------------------------------------
// Kernel 1: xa[t, 0..31] = x[t,:] @ A_buffer[idx[t]]  (fp32, float4 loads)
// ---------------------------------------------------------------------------
__global__ void xa_kernel(const float* __restrict__ x,
                          const float* __restrict__ A,
                          const int* __restrict__ idx) {
    __shared__ float xs[D_DIM];
    __shared__ float red[32][36];

    const int t = blockIdx.x;
    const int l = idx[t];
    const int tid = threadIdx.x;

    const float4* xr4 = (const float4*)(x + (size_t)t * D_DIM);
#pragma unroll
    for (int i = 0; i < 2; ++i)
        ((float4*)xs)[tid + i * 256] = xr4[tid + i * 256];
    __syncthreads();

    const int rq = tid & 7;
    const int slice = tid >> 3;
    const float4* A4 = (const float4*)(A + (size_t)l * D_DIM * 32);

    float4 acc = make_float4(0.f, 0.f, 0.f, 0.f);
#pragma unroll 4
    for (int i = 0; i < 64; ++i) {
        int d = slice * 64 + i;
        float4 a = A4[(size_t)d * 8 + rq];
        float xv = xs[d];
        acc.x = fmaf(xv, a.x, acc.x);
        acc.y = fmaf(xv, a.y, acc.y);
        acc.z = fmaf(xv, a.z, acc.z);
        acc.w = fmaf(xv, a.w, acc.w);
    }
    red[slice][rq * 4 + 0] = acc.x;
    red[slice][rq * 4 + 1] = acc.y;
    red[slice][rq * 4 + 2] = acc.z;
    red[slice][rq * 4 + 3] = acc.w;
    __syncthreads();

    if (tid < 32) {
        float s = 0.f;
#pragma unroll
        for (int k = 0; k < 32; ++k) s += red[k][tid];
        g_xa[t * 32 + tid] = s;
    }
}

// ---------------------------------------------------------------------------
// Kernel 2: tf32 mma.sync GEMM, 128x128 tile, 4 warps (2x2), 64x64 warp tile,
// 128 threads, 2 CTAs/SM. Smem traffic: 96KB/stage (was 128KB).
// ---------------------------------------------------------------------------
__device__ __forceinline__ void load_stage(uint32_t saA, uint32_t saB,
                                           const float* __restrict__ xg,
                                           const float* __restrict__ wg, int tid) {
#pragma unroll
    for (int i = 0; i < 8; ++i) {
        int idx = tid + i * NTHREADS;
        int row = idx >> 3, seg = idx & 7;
        CP_ASYNC16(saA + swz(row * 128 + seg * 16), xg + (size_t)row * D_DIM + seg * 4);
    }
#pragma unroll
    for (int i = 0; i < 8; ++i) {
        int idx = tid + i * NTHREADS;
        int row = idx >> 3, seg = idx & 7;
        CP_ASYNC16(saB + swz(row * 128 + seg * 16), wg + (size_t)row * D_DIM + seg * 4);
    }
}

__global__ __launch_bounds__(NTHREADS, 2)
void gemm_tc_kernel(const float* __restrict__ Bbuf,
                    const int* __restrict__ idx,
                    float* __restrict__ out) {
    extern __shared__ char sm[];
    const uint32_t sb = smem_u32(sm);

    const int tid = threadIdx.x;
    const int wid = tid >> 5, lane = tid & 31;
    const int wm = wid & 1;        // 2 warp-rows of 64
    const int wn = wid >> 1;       // 2 warp-cols of 64
    const int bm = blockIdx.y * BM;
    const int bn = blockIdx.x * BN;

    float* xa_s = (float*)(sm + OFF_XA);
    int*   ls   = (int*)(sm + OFF_LS);

    // delta metadata
    const int half = (bn >= BD) ? 1 : 0;
    for (int i = tid; i < BM * 16; i += NTHREADS) {
        int row = i >> 4, r = i & 15;
        xa_s[row * 16 + r] = g_xa[(bm + row) * 32 + half * 16 + r];
    }
    if (tid < BM) ls[tid] = idx[bm + tid];

    const float* xbase = g_x32 + (size_t)bm * D_DIM;
    const float* wbase = g_w32 + (size_t)bn * D_DIM;

    // prologue: stages 0..1
#pragma unroll
    for (int s = 0; s < NST - 1; ++s) {
        load_stage(sb + OFF_PIPE + s * STAGE_BYTES,
                   sb + OFF_PIPE + s * STAGE_BYTES + 16384,
                   xbase + s * BK, wbase + s * BK, tid);
        CP_COMMIT();
    }

    float acc[4][8][4];
#pragma unroll
    for (int mt = 0; mt < 4; ++mt)
#pragma unroll
        for (int nt = 0; nt < 8; ++nt)
#pragma unroll
            for (int j = 0; j < 4; ++j) acc[mt][nt][j] = 0.f;

    // ---- per-lane ldmatrix address components (layouts validated R4..R7) ----
    const int j8 = lane >> 3, lr = lane & 7;
    uint32_t a_off[4], a_xor[4], b_off[4], b_xor[4];
    const uint32_t a_cb = (j8 >> 1) * 16;
    const uint32_t b_cb = (j8 & 1) * 16;
#pragma unroll
    for (int mt = 0; mt < 4; ++mt) {
        uint32_t row = wm * 64 + mt * 16 + (j8 & 1) * 8 + lr;
        a_off[mt] = row * 128;
        a_xor[mt] = (row & 7) << 4;
    }
#pragma unroll
    for (int p = 0; p < 4; ++p) {
        uint32_t row = wn * 64 + p * 16 + (j8 >> 1) * 8 + lr;
        b_off[p] = row * 128;
        b_xor[p] = (row & 7) << 4;
    }

    int slot = 0;                        // stage slot of iteration s
    for (int s = 0; s < NSTEP; ++s) {
        CP_WAIT1();
        __syncthreads();                 // stage-s data visible; prev reads done

        if (s + NST - 1 < NSTEP) {
            int ld = slot + (NST - 1); if (ld >= NST) ld -= NST;
            load_stage(sb + OFF_PIPE + ld * STAGE_BYTES,
                       sb + OFF_PIPE + ld * STAGE_BYTES + 16384,
                       xbase + (s + NST - 1) * BK, wbase + (s + NST - 1) * BK, tid);
        }
        CP_COMMIT();

        const uint32_t Asb = sb + OFF_PIPE + slot * STAGE_BYTES;
        const uint32_t Bsb = Asb + 16384;

#pragma unroll
        for (int kk = 0; kk < 4; ++kk) {
            const uint32_t kb = kk * 32;
            uint32_t a[4][4], b[8][2];
#pragma unroll
            for (int mt = 0; mt < 4; ++mt) {
                uint32_t ad = Asb + a_off[mt] + ((kb + a_cb) ^ a_xor[mt]);
                LDSM_X4(a[mt][0], a[mt][1], a[mt][2], a[mt][3], ad);
            }
#pragma unroll
            for (int p = 0; p < 4; ++p) {
                uint32_t bd = Bsb + b_off[p] + ((kb + b_cb) ^ b_xor[p]);
                LDSM_X4(b[2 * p][0], b[2 * p][1], b[2 * p + 1][0], b[2 * p + 1][1], bd);
            }
#pragma unroll
            for (int mt = 0; mt < 4; ++mt)
#pragma unroll
                for (int nt = 0; nt < 8; ++nt)
                    mma_tf32(acc[mt][nt], a[mt], b[nt]);
        }
        if (++slot == NST) slot = 0;
    }

    // ---- stage accumulators to smem (reuse pipeline region), padded rows ----
    __syncthreads();
    float* Cs = (float*)(sm + OFF_PIPE);
    const int mrow = lane >> 2, kcol = lane & 3;
#pragma unroll
    for (int mt = 0; mt < 4; ++mt)
#pragma unroll
        for (int nt = 0; nt < 8; ++nt) {
            int row0 = wm * 64 + mt * 16 + mrow;
            int col  = wn * 64 + nt * 8 + kcol * 2;
            *(float2*)&Cs[row0 * 132 + col]       = make_float2(acc[mt][nt][0], acc[mt][nt][1]);
            *(float2*)&Cs[(row0 + 8) * 132 + col] = make_float2(acc[mt][nt][2], acc[mt][nt][3]);
        }
    __syncthreads();

    // ---- epilogue: row = tid; four 32-col passes, fused LoRA delta ----
    {
        const int row = tid;
        const int l   = ls[row];
        const float* xav = &xa_s[row * 16];

#pragma unroll
        for (int pass = 0; pass < 4; ++pass) {
            const int ch = pass * 32;
            float v[32];
#pragma unroll
            for (int j = 0; j < 8; ++j) {
                float4 t4 = *(const float4*)&Cs[row * 132 + ch + 4 * j];
                v[4 * j] = t4.x; v[4 * j + 1] = t4.y; v[4 * j + 2] = t4.z; v[4 * j + 3] = t4.w;
            }
            const float* Bp = Bbuf + (size_t)l * 16 * N_OUT + bn + ch;
#pragma unroll
            for (int r = 0; r < R_N; ++r) {
                float xv = xav[r];
                const float4* B4 = (const float4*)(Bp + (size_t)r * N_OUT);
#pragma unroll
                for (int j = 0; j < 8; ++j) {
                    float4 bb = B4[j];
                    v[4 * j + 0] = fmaf(xv, bb.x, v[4 * j + 0]);
                    v[4 * j + 1] = fmaf(xv, bb.y, v[4 * j + 1]);
                    v[4 * j + 2] = fmaf(xv, bb.z, v[4 * j + 2]);
                    v[4 * j + 3] = fmaf(xv, bb.w, v[4 * j + 3]);
                }
            }
            float* op = out + (size_t)(bm + row) * N_OUT + bn + ch;
#pragma unroll
            for (int j = 0; j < 8; ++j)
                ((float4*)op)[j] = make_float4(v[4 * j], v[4 * j + 1],
                                               v[4 * j + 2], v[4 * j + 3]);
        }
    }
}

// ---------------------------------------------------------------------------
extern "C" void kernel_launch(void* const* d_in, const int* in_sizes, int n_in,
                              void* d_out, int out_size) {
    const float* x    = (const float*)d_in[0];
    const float* W    = (const float*)d_in[1];
    const float* Abuf = (const float*)d_in[2];
    const float* Bbuf = (const float*)d_in[3];
    const int*   idx  = (const int*)d_in[4];
    float*       out  = (float*)d_out;

    cudaFuncSetAttribute(gemm_tc_kernel,
                         cudaFuncAttributeMaxDynamicSharedMemorySize, SMEM_BYTES);

    cvt_kernel<<<1024, 256>>>(x, W);
    xa_kernel<<<T_TOK, 256>>>(x, Abuf, idx);

    dim3 grid(N_OUT / BN, T_TOK / BM);   // 88 x 16
    gemm_tc_kernel<<<grid, NTHREADS, SMEM_BYTES>>>(Bbuf, idx, out);
}

// round 11
// speedup vs baseline: 1.7858x; 1.3811x over previous
#include <cuda_runtime.h>
#include <cuda_fp16.h>
#include <cstdint>

// ---------------- problem constants ----------------
#define T_TOK 2048
#define D_DIM 2048
#define N_OUT 11264
#define R_N   16
#define BD    5632

// ---------------- GEMM config ----------------
#define BM 128
#define BN 128
#define BK 64                  // K per stage (64 fp16 = 128B row)
#define NST 3                  // cp.async pipeline stages
#define NSTEP (D_DIM / BK)     // 32
#define NTHREADS 128           // 4 warps, 64x64 warp tiles (2x2)

// smem layout (byte offsets into dynamic smem)
#define OFF_LS   0             // 128 ints
#define OFF_XA   512           // 128*16 floats = 8192
#define OFF_PIPE 9216          // NST * 32768 (A 16K + B 16K per stage)
#define STAGE_BYTES 32768
#define SMEM_BYTES (OFF_PIPE + NST * STAGE_BYTES)   // 107520 -> 2 CTAs/SM

__device__ float  g_xa[T_TOK * 32];
__device__ __half g_x16[(size_t)T_TOK * D_DIM];   // x in fp16
__device__ __half g_w16[(size_t)N_OUT * D_DIM];   // W in fp16

// ---------------- helpers ----------------
__device__ __forceinline__ uint32_t smem_u32(const void* p) {
    uint32_t a;
    asm("{ .reg .u64 t; cvta.to.shared.u64 t, %1; cvt.u32.u64 %0, t; }" : "=r"(a) : "l"(p));
    return a;
}
#define CP_ASYNC16(dst, src) \
    asm volatile("cp.async.cg.shared.global [%0], [%1], 16;" :: "r"(dst), "l"(src) : "memory")
#define CP_COMMIT() asm volatile("cp.async.commit_group;" ::: "memory")
#define CP_WAIT1()  asm volatile("cp.async.wait_group 1;" ::: "memory")

__device__ __forceinline__ uint32_t swz(uint32_t off) { return off ^ ((off >> 3) & 0x70); }

#define LDSM_X4(r0, r1, r2, r3, addr) \
    asm volatile("ldmatrix.sync.aligned.m8n8.x4.shared.b16 {%0,%1,%2,%3}, [%4];" \
                 : "=r"(r0), "=r"(r1), "=r"(r2), "=r"(r3) : "r"(addr))

__device__ __forceinline__ void mma_f16(float* c, const uint32_t* a, const uint32_t* b) {
    asm volatile("mma.sync.aligned.m16n8k16.row.col.f32.f16.f16.f32 "
        "{%0,%1,%2,%3}, {%4,%5,%6,%7}, {%8,%9}, {%0,%1,%2,%3};"
        : "+f"(c[0]), "+f"(c[1]), "+f"(c[2]), "+f"(c[3])
        : "r"(a[0]), "r"(a[1]), "r"(a[2]), "r"(a[3]), "r"(b[0]), "r"(b[1]));
}

// ---------------------------------------------------------------------------
// Kernel 0: convert x and W to fp16 once (RN).
// ---------------------------------------------------------------------------
__global__ void cvt_kernel(const float* __restrict__ x, const float* __restrict__ W) {
    const size_t NX4 = (size_t)T_TOK * D_DIM / 4;
    const size_t NW4 = (size_t)N_OUT * D_DIM / 4;
    const size_t stride = (size_t)gridDim.x * blockDim.x;
    for (size_t p = (size_t)blockIdx.x * blockDim.x + threadIdx.x; p < NX4 + NW4; p += stride) {
        float4 v = (p < NX4) ? ((const float4*)x)[p] : ((const float4*)W)[p - NX4];
        __half2 h0 = __floats2half2_rn(v.x, v.y);
        __half2 h1 = __floats2half2_rn(v.z, v.w);
        uint2 o = make_uint2(*(uint32_t*)&h0, *(uint32_t*)&h1);
        uint2* dst = (p < NX4) ? ((uint2*)g_x16) + p : ((uint2*)g_w16) + (p - NX4);
        *dst = o;
    }
}

// ---------------------------------------------------------------------------
// Kernel 1: xa[t, 0..31] = x[t,:] @ A_buffer[idx[t]]  (fp32, float4 loads)
// ---------------------------------------------------------------------------
__global__ void xa_kernel(const float* __restrict__ x,
                          const float* __restrict__ A,
                          const int* __restrict__ idx) {
    __shared__ float xs[D_DIM];
    __shared__ float red[32][36];

    const int t = blockIdx.x;
    const int l = idx[t];
    const int tid = threadIdx.x;

    const float4* xr4 = (const float4*)(x + (size_t)t * D_DIM);
#pragma unroll
    for (int i = 0; i < 2; ++i)
        ((float4*)xs)[tid + i * 256] = xr4[tid + i * 256];
    __syncthreads();

    const int rq = tid & 7;
    const int slice = tid >> 3;
    const float4* A4 = (const float4*)(A + (size_t)l * D_DIM * 32);

    float4 acc = make_float4(0.f, 0.f, 0.f, 0.f);
#pragma unroll 4
    for (int i = 0; i < 64; ++i) {
        int d = slice * 64 + i;
        float4 a = A4[(size_t)d * 8 + rq];
        float xv = xs[d];
        acc.x = fmaf(xv, a.x, acc.x);
        acc.y = fmaf(xv, a.y, acc.y);
        acc.z = fmaf(xv, a.z, acc.z);
        acc.w = fmaf(xv, a.w, acc.w);
    }
    red[slice][rq * 4 + 0] = acc.x;
    red[slice][rq * 4 + 1] = acc.y;
    red[slice][rq * 4 + 2] = acc.z;
    red[slice][rq * 4 + 3] = acc.w;
    __syncthreads();

    if (tid < 32) {
        float s = 0.f;
#pragma unroll
        for (int k = 0; k < 32; ++k) s += red[k][tid];
        g_xa[t * 32 + tid] = s;
    }
}

// ---------------------------------------------------------------------------
// Kernel 2: fp16 m16n8k16 GEMM, 128x128 tile, 4 warps (2x2), 64x64 warp tile,
// BK=64 per stage (32 stages), 2 CTAs/SM.
// ---------------------------------------------------------------------------
__device__ __forceinline__ void load_stage(uint32_t saA, uint32_t saB,
                                           const __half* __restrict__ xg,
                                           const __half* __restrict__ wg, int tid) {
#pragma unroll
    for (int i = 0; i < 8; ++i) {
        int idx = tid + i * NTHREADS;
        int row = idx >> 3, seg = idx & 7;
        CP_ASYNC16(saA + swz(row * 128 + seg * 16), xg + (size_t)row * D_DIM + seg * 8);
    }
#pragma unroll
    for (int i = 0; i < 8; ++i) {
        int idx = tid + i * NTHREADS;
        int row = idx >> 3, seg = idx & 7;
        CP_ASYNC16(saB + swz(row * 128 + seg * 16), wg + (size_t)row * D_DIM + seg * 8);
    }
}

__global__ __launch_bounds__(NTHREADS, 2)
void gemm_tc_kernel(const float* __restrict__ Bbuf,
                    const int* __restrict__ idx,
                    float* __restrict__ out) {
    extern __shared__ char sm[];
    const uint32_t sb = smem_u32(sm);

    const int tid = threadIdx.x;
    const int wid = tid >> 5, lane = tid & 31;
    const int wm = wid & 1;        // 2 warp-rows of 64
    const int wn = wid >> 1;       // 2 warp-cols of 64
    const int bm = blockIdx.y * BM;
    const int bn = blockIdx.x * BN;

    float* xa_s = (float*)(sm + OFF_XA);
    int*   ls   = (int*)(sm + OFF_LS);

    // delta metadata
    const int half = (bn >= BD) ? 1 : 0;
    for (int i = tid; i < BM * 16; i += NTHREADS) {
        int row = i >> 4, r = i & 15;
        xa_s[row * 16 + r] = g_xa[(bm + row) * 32 + half * 16 + r];
    }
    if (tid < BM) ls[tid] = idx[bm + tid];

    const __half* xbase = g_x16 + (size_t)bm * D_DIM;
    const __half* wbase = g_w16 + (size_t)bn * D_DIM;

    // prologue: stages 0..1
#pragma unroll
    for (int s = 0; s < NST - 1; ++s) {
        load_stage(sb + OFF_PIPE + s * STAGE_BYTES,
                   sb + OFF_PIPE + s * STAGE_BYTES + 16384,
                   xbase + s * BK, wbase + s * BK, tid);
        CP_COMMIT();
    }

    float acc[4][8][4];
#pragma unroll
    for (int mt = 0; mt < 4; ++mt)
#pragma unroll
        for (int nt = 0; nt < 8; ++nt)
#pragma unroll
            for (int j = 0; j < 4; ++j) acc[mt][nt][j] = 0.f;

    // ---- per-lane ldmatrix address components ----
    // A m16k16 tile mt: x4 matrices (m0k0, m8k0, m0k8, m8k8):
    //   row = wm*64 + mt*16 + (j8&1)*8 + lr, col-bytes = kk*32 + (j8>>1)*16
    // B n16 pair p: x4 matrices (n0k0, n0k8, n8k0, n8k8):
    //   row = wn*64 + p*16 + (j8>>1)*8 + lr, col-bytes = kk*32 + (j8&1)*16
    const int j8 = lane >> 3, lr = lane & 7;
    uint32_t a_off[4], a_xor[4], b_off[4], b_xor[4];
    const uint32_t a_cb = (j8 >> 1) * 16;
    const uint32_t b_cb = (j8 & 1) * 16;
#pragma unroll
    for (int mt = 0; mt < 4; ++mt) {
        uint32_t row = wm * 64 + mt * 16 + (j8 & 1) * 8 + lr;
        a_off[mt] = row * 128;
        a_xor[mt] = (row & 7) << 4;
    }
#pragma unroll
    for (int p = 0; p < 4; ++p) {
        uint32_t row = wn * 64 + p * 16 + (j8 >> 1) * 8 + lr;
        b_off[p] = row * 128;
        b_xor[p] = (row & 7) << 4;
    }

    int slot = 0;                        // stage slot of iteration s
    for (int s = 0; s < NSTEP; ++s) {
        CP_WAIT1();
        __syncthreads();                 // stage-s data visible; prev reads done

        if (s + NST - 1 < NSTEP) {
            int ld = slot + (NST - 1); if (ld >= NST) ld -= NST;
            load_stage(sb + OFF_PIPE + ld * STAGE_BYTES,
                       sb + OFF_PIPE + ld * STAGE_BYTES + 16384,
                       xbase + (s + NST - 1) * BK, wbase + (s + NST - 1) * BK, tid);
        }
        CP_COMMIT();

        const uint32_t Asb = sb + OFF_PIPE + slot * STAGE_BYTES;
        const uint32_t Bsb = Asb + 16384;

#pragma unroll
        for (int kk = 0; kk < 4; ++kk) {
            const uint32_t kb = kk * 32;               // k16 of fp16 = 32 bytes
            uint32_t a[4][4], b[8][2];
#pragma unroll
            for (int mt = 0; mt < 4; ++mt) {
                uint32_t ad = Asb + a_off[mt] + ((kb + a_cb) ^ a_xor[mt]);
                LDSM_X4(a[mt][0], a[mt][1], a[mt][2], a[mt][3], ad);
            }
#pragma unroll
            for (int p = 0; p < 4; ++p) {
                uint32_t bd = Bsb + b_off[p] + ((kb + b_cb) ^ b_xor[p]);
                LDSM_X4(b[2 * p][0], b[2 * p][1], b[2 * p + 1][0], b[2 * p + 1][1], bd);
            }
#pragma unroll
            for (int mt = 0; mt < 4; ++mt)
#pragma unroll
                for (int nt = 0; nt < 8; ++nt)
                    mma_f16(acc[mt][nt], a[mt], b[nt]);
        }
        if (++slot == NST) slot = 0;
    }

    // ---- stage accumulators to smem (reuse pipeline region), padded rows ----
    __syncthreads();
    float* Cs = (float*)(sm + OFF_PIPE);
    const int mrow = lane >> 2, kcol = lane & 3;
#pragma unroll
    for (int mt = 0; mt < 4; ++mt)
#pragma unroll
        for (int nt = 0; nt < 8; ++nt) {
            int row0 = wm * 64 + mt * 16 + mrow;
            int col  = wn * 64 + nt * 8 + kcol * 2;
            *(float2*)&Cs[row0 * 132 + col]       = make_float2(acc[mt][nt][0], acc[mt][nt][1]);
            *(float2*)&Cs[(row0 + 8) * 132 + col] = make_float2(acc[mt][nt][2], acc[mt][nt][3]);
        }
    __syncthreads();

    // ---- epilogue: row = tid; four 32-col passes, fused LoRA delta ----
    {
        const int row = tid;
        const int l   = ls[row];
        const float* xav = &xa_s[row * 16];

#pragma unroll
        for (int pass = 0; pass < 4; ++pass) {
            const int ch = pass * 32;
            float v[32];
#pragma unroll
            for (int j = 0; j < 8; ++j) {
                float4 t4 = *(const float4*)&Cs[row * 132 + ch + 4 * j];
                v[4 * j] = t4.x; v[4 * j + 1] = t4.y; v[4 * j + 2] = t4.z; v[4 * j + 3] = t4.w;
            }
            const float* Bp = Bbuf + (size_t)l * 16 * N_OUT + bn + ch;
#pragma unroll
            for (int r = 0; r < R_N; ++r) {
                float xv = xav[r];
                const float4* B4 = (const float4*)(Bp + (size_t)r * N_OUT);
#pragma unroll
                for (int j = 0; j < 8; ++j) {
                    float4 bb = B4[j];
                    v[4 * j + 0] = fmaf(xv, bb.x, v[4 * j + 0]);
                    v[4 * j + 1] = fmaf(xv, bb.y, v[4 * j + 1]);
                    v[4 * j + 2] = fmaf(xv, bb.z, v[4 * j + 2]);
                    v[4 * j + 3] = fmaf(xv, bb.w, v[4 * j + 3]);
                }
            }
            float* op = out + (size_t)(bm + row) * N_OUT + bn + ch;
#pragma unroll
            for (int j = 0; j < 8; ++j)
                ((float4*)op)[j] = make_float4(v[4 * j], v[4 * j + 1],
                                               v[4 * j + 2], v[4 * j + 3]);
        }
    }
}

// ---------------------------------------------------------------------------
extern "C" void kernel_launch(void* const* d_in, const int* in_sizes, int n_in,
                              void* d_out, int out_size) {
    const float* x    = (const float*)d_in[0];
    const float* W    = (const float*)d_in[1];
    const float* Abuf = (const float*)d_in[2];
    const float* Bbuf = (const float*)d_in[3];
    const int*   idx  = (const int*)d_in[4];
    float*       out  = (float*)d_out;

    cudaFuncSetAttribute(gemm_tc_kernel,
                         cudaFuncAttributeMaxDynamicSharedMemorySize, SMEM_BYTES);

    cvt_kernel<<<1024, 256>>>(x, W);
    xa_kernel<<<T_TOK, 256>>>(x, Abuf, idx);

    dim3 grid(N_OUT / BN, T_TOK / BM);   // 88 x 16
    gemm_tc_kernel<<<grid, NTHREADS, SMEM_BYTES>>>(Bbuf, idx, out);
}

// round 12
// speedup vs baseline: 1.8784x; 1.0518x over previous
#include <cuda_runtime.h>
#include <cuda_fp16.h>
#include <cstdint>

// ---------------- problem constants ----------------
#define T_TOK 2048
#define D_DIM 2048
#define N_OUT 11264
#define R_N   16
#define BD    5632

// ---------------- GEMM config ----------------
#define BM 128
#define BN 128
#define BK 64                  // K per stage (64 fp16 = 128B row)
#define NST 3                  // pipeline stages
#define NSTEP (D_DIM / BK)     // 32
#define NTHREADS 128           // 4 warps, 64x64 warp tiles (2x2)
#define NTILE_K 32             // stages per tile row block

// smem layout (byte offsets into dynamic smem)
#define OFF_MBAR 0             // NST * 8
#define OFF_LS   64            // 128 ints
#define OFF_XA   576           // 128*16 floats = 8192 (ends 8768)
#define OFF_PIPE 9216          // NST * 32768 (A 16K + B 16K per stage)
#define STAGE_BYTES 32768
#define SMEM_BYTES (OFF_PIPE + NST * STAGE_BYTES)   // 107520 -> 2 CTAs/SM

__device__ float g_xa[T_TOK * 32];
// blocked+swizzled fp16 copies: [tile][stage][128 rows x 128B, SW128]
__device__ uint4 g_x16s[(size_t)(T_TOK / 128) * NTILE_K * 1024];   // 8 MB
__device__ uint4 g_w16s[(size_t)(N_OUT / 128) * NTILE_K * 1024];   // 46 MB

// ---------------- helpers ----------------
__device__ __forceinline__ uint32_t smem_u32(const void* p) {
    uint32_t a;
    asm("{ .reg .u64 t; cvta.to.shared.u64 t, %1; cvt.u32.u64 %0, t; }" : "=r"(a) : "l"(p));
    return a;
}
__device__ __forceinline__ uint32_t swz(uint32_t off) { return off ^ ((off >> 3) & 0x70); }

#define MBAR_INIT(addr, cnt) \
    asm volatile("mbarrier.init.shared.b64 [%0], %1;" :: "r"(addr), "r"(cnt) : "memory")
#define MBAR_EXPECT_TX(addr, bytes) \
    asm volatile("mbarrier.arrive.expect_tx.shared.b64 _, [%0], %1;" :: "r"(addr), "r"(bytes) : "memory")
#define MBAR_WAIT(addr, par) do {                                               \
    uint32_t _m = (addr), _p = (par), _d;                                       \
    asm volatile("{ .reg .pred p; mbarrier.try_wait.parity.acquire.cta.shared::cta.b64 p, [%1], %2;" \
                 " selp.b32 %0, 1, 0, p; }" : "=r"(_d) : "r"(_m), "r"(_p) : "memory"); \
    if (!_d) {                                                                  \
        asm volatile("{ .reg .pred P1; WL%=: mbarrier.try_wait.parity.acquire.cta.shared::cta.b64 P1, [%0], %1, 0x989680;" \
                     " @P1 bra.uni WD%=; bra.uni WL%=; WD%=: }" :: "r"(_m), "r"(_p) : "memory"); \
    } } while (0)

#define CP_BULK(dst, src, bytes, mbar) \
    asm volatile("cp.async.bulk.shared::cta.global.mbarrier::complete_tx::bytes [%0], [%1], %2, [%3];" \
                 :: "r"(dst), "l"(src), "r"(bytes), "r"(mbar) : "memory")

#define LDSM_X4(r0, r1, r2, r3, addr) \
    asm volatile("ldmatrix.sync.aligned.m8n8.x4.shared.b16 {%0,%1,%2,%3}, [%4];" \
                 : "=r"(r0), "=r"(r1), "=r"(r2), "=r"(r3) : "r"(addr))

__device__ __forceinline__ void mma_f16(float* c, const uint32_t* a, const uint32_t* b) {
    asm volatile("mma.sync.aligned.m16n8k16.row.col.f32.f16.f16.f32 "
        "{%0,%1,%2,%3}, {%4,%5,%6,%7}, {%8,%9}, {%0,%1,%2,%3};"
        : "+f"(c[0]), "+f"(c[1]), "+f"(c[2]), "+f"(c[3])
        : "r"(a[0]), "r"(a[1]), "r"(a[2]), "r"(a[3]), "r"(b[0]), "r"(b[1]));
}

// ---------------------------------------------------------------------------
// Kernel 0: fp16-convert x and W into blocked, SW128-swizzled tile layout.
// One 16B chunk per loop iteration: row-major source, blocked destination.
// ---------------------------------------------------------------------------
__global__ void cvt_kernel(const float* __restrict__ x, const float* __restrict__ W) {
    const size_t CX = (size_t)T_TOK * 256;   // 16B chunks of x (256 per row)
    const size_t CW = (size_t)N_OUT * 256;
    const size_t stride = (size_t)gridDim.x * blockDim.x;
    for (size_t c = (size_t)blockIdx.x * blockDim.x + threadIdx.x; c < CX + CW; c += stride) {
        const float* src;
        uint4* dstbase;
        size_t cc;
        if (c < CX) { cc = c; src = x; dstbase = g_x16s; }
        else        { cc = c - CX; src = W; dstbase = g_w16s; }
        const int row  = (int)(cc >> 8);
        const int kseg = (int)(cc & 255);
        const int tile = row >> 7, r = row & 127;
        const int stage = kseg >> 3, seg = kseg & 7;

        const float4* s4 = (const float4*)(src + (size_t)row * D_DIM + kseg * 8);
        float4 v0 = s4[0], v1 = s4[1];
        __half2 h0 = __floats2half2_rn(v0.x, v0.y);
        __half2 h1 = __floats2half2_rn(v0.z, v0.w);
        __half2 h2 = __floats2half2_rn(v1.x, v1.y);
        __half2 h3 = __floats2half2_rn(v1.z, v1.w);
        uint4 o = make_uint4(*(uint32_t*)&h0, *(uint32_t*)&h1,
                             *(uint32_t*)&h2, *(uint32_t*)&h3);
        uint32_t boff = swz((uint32_t)(r * 128 + seg * 16));
        dstbase[(size_t)(tile * NTILE_K + stage) * 1024 + (boff >> 4)] = o;
    }
}

// ---------------------------------------------------------------------------
// Kernel 1: xa[t, 0..31] = x[t,:] @ A_buffer[idx[t]]  (fp32, float4 loads)
// ---------------------------------------------------------------------------
__global__ void xa_kernel(const float* __restrict__ x,
                          const float* __restrict__ A,
                          const int* __restrict__ idx) {
    __shared__ float xs[D_DIM];
    __shared__ float red[32][36];

    const int t = blockIdx.x;
    const int l = idx[t];
    const int tid = threadIdx.x;

    const float4* xr4 = (const float4*)(x + (size_t)t * D_DIM);
#pragma unroll
    for (int i = 0; i < 2; ++i)
        ((float4*)xs)[tid + i * 256] = xr4[tid + i * 256];
    __syncthreads();

    const int rq = tid & 7;
    const int slice = tid >> 3;
    const float4* A4 = (const float4*)(A + (size_t)l * D_DIM * 32);

    float4 acc = make_float4(0.f, 0.f, 0.f, 0.f);
#pragma unroll 4
    for (int i = 0; i < 64; ++i) {
        int d = slice * 64 + i;
        float4 a = A4[(size_t)d * 8 + rq];
        float xv = xs[d];
        acc.x = fmaf(xv, a.x, acc.x);
        acc.y = fmaf(xv, a.y, acc.y);
        acc.z = fmaf(xv, a.z, acc.z);
        acc.w = fmaf(xv, a.w, acc.w);
    }
    red[slice][rq * 4 + 0] = acc.x;
    red[slice][rq * 4 + 1] = acc.y;
    red[slice][rq * 4 + 2] = acc.z;
    red[slice][rq * 4 + 3] = acc.w;
    __syncthreads();

    if (tid < 32) {
        float s = 0.f;
#pragma unroll
        for (int k = 0; k < 32; ++k) s += red[k][tid];
        g_xa[t * 32 + tid] = s;
    }
}

// ---------------------------------------------------------------------------
// Kernel 2: fp16 m16n8k16 GEMM; stages delivered by cp.async.bulk + mbarrier.
// 128x128 tile, 4 warps (2x2), 64x64 warp tile, 2 CTAs/SM.
// ---------------------------------------------------------------------------
__global__ __launch_bounds__(NTHREADS, 2)
void gemm_tc_kernel(const float* __restrict__ Bbuf,
                    const int* __restrict__ idx,
                    float* __restrict__ out) {
    extern __shared__ char sm[];
    const uint32_t sb = smem_u32(sm);

    const int tid = threadIdx.x;
    const int wid = tid >> 5, lane = tid & 31;
    const int wm = wid & 1;        // 2 warp-rows of 64
    const int wn = wid >> 1;       // 2 warp-cols of 64
    const int bm = blockIdx.y * BM;
    const int bn = blockIdx.x * BN;

    float* xa_s = (float*)(sm + OFF_XA);
    int*   ls   = (int*)(sm + OFF_LS);

    if (tid == 0) {
#pragma unroll
        for (int i = 0; i < NST; ++i) MBAR_INIT(sb + OFF_MBAR + 8 * i, 1);
    }

    // delta metadata
    const int half = (bn >= BD) ? 1 : 0;
    for (int i = tid; i < BM * 16; i += NTHREADS) {
        int row = i >> 4, r = i & 15;
        xa_s[row * 16 + r] = g_xa[(bm + row) * 32 + half * 16 + r];
    }
    if (tid < BM) ls[tid] = idx[bm + tid];
    __syncthreads();   // mbarriers initialized before any expect/bulk

    const char* xsrc = (const char*)g_x16s + (size_t)(blockIdx.y * NTILE_K) * 16384;
    const char* wsrc = (const char*)g_w16s + (size_t)(blockIdx.x * NTILE_K) * 16384;

    // prologue: stages 0..1
    if (tid == 0) {
#pragma unroll
        for (int s = 0; s < NST - 1; ++s) {
            uint32_t mb = sb + OFF_MBAR + 8 * s;
            MBAR_EXPECT_TX(mb, STAGE_BYTES);
            CP_BULK(sb + OFF_PIPE + s * STAGE_BYTES,          xsrc + (size_t)s * 16384, 16384, mb);
            CP_BULK(sb + OFF_PIPE + s * STAGE_BYTES + 16384,  wsrc + (size_t)s * 16384, 16384, mb);
        }
    }

    float acc[4][8][4];
#pragma unroll
    for (int mt = 0; mt < 4; ++mt)
#pragma unroll
        for (int nt = 0; nt < 8; ++nt)
#pragma unroll
            for (int j = 0; j < 4; ++j) acc[mt][nt][j] = 0.f;

    // ---- per-lane ldmatrix address components (validated R4..R10) ----
    const int j8 = lane >> 3, lr = lane & 7;
    uint32_t a_off[4], a_xor[4], b_off[4], b_xor[4];
    const uint32_t a_cb = (j8 >> 1) * 16;
    const uint32_t b_cb = (j8 & 1) * 16;
#pragma unroll
    for (int mt = 0; mt < 4; ++mt) {
        uint32_t row = wm * 64 + mt * 16 + (j8 & 1) * 8 + lr;
        a_off[mt] = row * 128;
        a_xor[mt] = (row & 7) << 4;
    }
#pragma unroll
    for (int p = 0; p < 4; ++p) {
        uint32_t row = wn * 64 + p * 16 + (j8 >> 1) * 8 + lr;
        b_off[p] = row * 128;
        b_xor[p] = (row & 7) << 4;
    }

    int slot = 0, par = 0;
    for (int s = 0; s < NSTEP; ++s) {
        MBAR_WAIT(sb + OFF_MBAR + 8 * slot, (uint32_t)par);

        // producer: refill the slot consumed at iteration s-1 with stage s+2
        if (tid == 0 && s + NST - 1 < NSTEP) {
            int lsg = s + NST - 1;
            int lslot = lsg % NST;
            uint32_t mb = sb + OFF_MBAR + 8 * lslot;
            MBAR_EXPECT_TX(mb, STAGE_BYTES);
            CP_BULK(sb + OFF_PIPE + lslot * STAGE_BYTES,         xsrc + (size_t)lsg * 16384, 16384, mb);
            CP_BULK(sb + OFF_PIPE + lslot * STAGE_BYTES + 16384, wsrc + (size_t)lsg * 16384, 16384, mb);
        }

        const uint32_t Asb = sb + OFF_PIPE + slot * STAGE_BYTES;
        const uint32_t Bsb = Asb + 16384;

#pragma unroll
        for (int kk = 0; kk < 4; ++kk) {
            const uint32_t kb = kk * 32;               // k16 of fp16 = 32 bytes
            uint32_t a[4][4], b[8][2];
#pragma unroll
            for (int mt = 0; mt < 4; ++mt) {
                uint32_t ad = Asb + a_off[mt] + ((kb + a_cb) ^ a_xor[mt]);
                LDSM_X4(a[mt][0], a[mt][1], a[mt][2], a[mt][3], ad);
            }
#pragma unroll
            for (int p = 0; p < 4; ++p) {
                uint32_t bd = Bsb + b_off[p] + ((kb + b_cb) ^ b_xor[p]);
                LDSM_X4(b[2 * p][0], b[2 * p][1], b[2 * p + 1][0], b[2 * p + 1][1], bd);
            }
#pragma unroll
            for (int mt = 0; mt < 4; ++mt)
#pragma unroll
                for (int nt = 0; nt < 8; ++nt)
                    mma_f16(acc[mt][nt], a[mt], b[nt]);
        }
        if (++slot == NST) { slot = 0; par ^= 1; }
        __syncthreads();   // all reads of this slot done before tid0 refills it
    }

    // ---- stage accumulators to smem (reuse pipeline region), padded rows ----
    float* Cs = (float*)(sm + OFF_PIPE);
    const int mrow = lane >> 2, kcol = lane & 3;
#pragma unroll
    for (int mt = 0; mt < 4; ++mt)
#pragma unroll
        for (int nt = 0; nt < 8; ++nt) {
            int row0 = wm * 64 + mt * 16 + mrow;
            int col  = wn * 64 + nt * 8 + kcol * 2;
            *(float2*)&Cs[row0 * 132 + col]       = make_float2(acc[mt][nt][0], acc[mt][nt][1]);
            *(float2*)&Cs[(row0 + 8) * 132 + col] = make_float2(acc[mt][nt][2], acc[mt][nt][3]);
        }
    __syncthreads();

    // ---- epilogue: row = tid; four 32-col passes, fused LoRA delta ----
    {
        const int row = tid;
        const int l   = ls[row];
        const float* xav = &xa_s[row * 16];

#pragma unroll
        for (int pass = 0; pass < 4; ++pass) {
            const int ch = pass * 32;
            float v[32];
#pragma unroll
            for (int j = 0; j < 8; ++j) {
                float4 t4 = *(const float4*)&Cs[row * 132 + ch + 4 * j];
                v[4 * j] = t4.x; v[4 * j + 1] = t4.y; v[4 * j + 2] = t4.z; v[4 * j + 3] = t4.w;
            }
            const float* Bp = Bbuf + (size_t)l * 16 * N_OUT + bn + ch;
#pragma unroll
            for (int r = 0; r < R_N; ++r) {
                float xv = xav[r];
                const float4* B4 = (const float4*)(Bp + (size_t)r * N_OUT);
#pragma unroll
                for (int j = 0; j < 8; ++j) {
                    float4 bb = B4[j];
                    v[4 * j + 0] = fmaf(xv, bb.x, v[4 * j + 0]);
                    v[4 * j + 1] = fmaf(xv, bb.y, v[4 * j + 1]);
                    v[4 * j + 2] = fmaf(xv, bb.z, v[4 * j + 2]);
                    v[4 * j + 3] = fmaf(xv, bb.w, v[4 * j + 3]);
                }
            }
            float* op = out + (size_t)(bm + row) * N_OUT + bn + ch;
#pragma unroll
            for (int j = 0; j < 8; ++j)
                ((float4*)op)[j] = make_float4(v[4 * j], v[4 * j + 1],
                                               v[4 * j + 2], v[4 * j + 3]);
        }
    }
}

// ---------------------------------------------------------------------------
extern "C" void kernel_launch(void* const* d_in, const int* in_sizes, int n_in,
                              void* d_out, int out_size) {
    const float* x    = (const float*)d_in[0];
    const float* W    = (const float*)d_in[1];
    const float* Abuf = (const float*)d_in[2];
    const float* Bbuf = (const float*)d_in[3];
    const int*   idx  = (const int*)d_in[4];
    float*       out  = (float*)d_out;

    cudaFuncSetAttribute(gemm_tc_kernel,
                         cudaFuncAttributeMaxDynamicSharedMemorySize, SMEM_BYTES);

    cvt_kernel<<<1024, 256>>>(x, W);
    xa_kernel<<<T_TOK, 256>>>(x, Abuf, idx);

    dim3 grid(N_OUT / BN, T_TOK / BM);   // 88 x 16
    gemm_tc_kernel<<<grid, NTHREADS, SMEM_BYTES>>>(Bbuf, idx, out);
}